// round 6
// baseline (speedup 1.0000x reference)
#include <cuda_runtime.h>

#define B_ 8
#define N_ 4096
#define KNN 20
#define PTS (B_*N_)
#define FULLMASK 0xFFFFFFFFu
typedef unsigned long long ull;

// ---------------- static device scratch (no allocation) ----------------
__device__ float2   g_xp[3*PTS];     // SoA channel pairs per point
__device__ float    g_xx[PTS];       // squared norms
__device__ float    g_nb[PTS*64];    // x . W1[:, :6]^T
__device__ float    g_cc[PTS*64];    // x . (W1[:,6:]-W1[:, :6])^T
__device__ int      g_idx[PTS*KNN];  // knn indices (within batch)
__device__ float    g_m2[PTS*128];   // max_k z2 (pre-BN)
__device__ float    g_s[2432];       // stats: s1[64] ss1[64] s2[128] ss2[128] s3[1024] ss3[1024]
__device__ float    g_ab[384];       // BN affine: a1[64] b1[64] a2[128] b2[128]
__device__ unsigned g_z3e[B_*1024];  // encoded max_n z3
__device__ float    g_g[B_*1024];    // global feature (after bn3+lrelu)
__device__ float    g_g4[B_*512];    // after fc1+bn4+lrelu
__device__ float    g_mat[B_*9];
__device__ float    g_bias[B_*3];
__device__ int      g_c0 = 0;        // stats1 completion counter
__device__ int      g_c1 = 0;        // conv2 completion counter
__device__ int      g_c2 = 0;        // conv3 completion counter

__device__ __forceinline__ float lrelu(float x){ return x >= 0.f ? x : 0.2f*x; }
__device__ __forceinline__ unsigned fenc(float f){
    unsigned u = __float_as_uint(f);
    return (u & 0x80000000u) ? ~u : (u | 0x80000000u);
}
__device__ __forceinline__ float fdec(unsigned u){
    u = (u & 0x80000000u) ? (u & 0x7FFFFFFFu) : ~u;
    return __uint_as_float(u);
}
__device__ __forceinline__ float f2lo(ull v){ return __uint_as_float((unsigned)v); }
__device__ __forceinline__ float f2hi(ull v){ return __uint_as_float((unsigned)(v>>32)); }
__device__ __forceinline__ void ffma2(ull& d, ull a, ull b){
    asm("fma.rn.f32x2 %0, %1, %2, %0;" : "+l"(d) : "l"(a), "l"(b));
}
__device__ __forceinline__ void fadd2(ull& d, ull b){
    asm("add.rn.f32x2 %0, %0, %1;" : "+l"(d) : "l"(b));
}

// ---------------- kernel: zero stats buffers (launch slot 2) ----------------
__global__ void k_zero2(){
    int t = threadIdx.x;
    for (int i = t; i < 2432; i += 256) g_s[i] = 0.f;
    for (int i = t; i < B_*1024; i += 256) g_z3e[i] = 0u;
}
// ---------------- no-op (launch slot 3; positions knn at slot 4 for ncu) ----
__global__ void k_nop(){}

// ---------------- kernel 1: transpose + norms + conv1 precompute ----------------
__global__ void k_prep(const float* __restrict__ x, const float* __restrict__ w1){
    __shared__ float wa[384], wd[384];
    int t = threadIdx.x;
    for (int i = t; i < 384; i += 256){
        int o = i/6, c = i%6;
        float a = w1[o*12 + c];
        wa[i] = a;
        wd[i] = w1[o*12 + 6 + c] - a;
    }
    __syncthreads();

    int p = blockIdx.x*256 + t;            // 128 blocks x 256 = 32768
    {
        int b = p >> 12, n = p & 4095;
        const float* xb = x + b*6*N_ + n;
        float x0=xb[0], x1=xb[N_], x2=xb[2*N_], x3=xb[3*N_], x4=xb[4*N_], x5=xb[5*N_];
        g_xp[p]       = make_float2(x0,x1);
        g_xp[PTS+p]   = make_float2(x2,x3);
        g_xp[2*PTS+p] = make_float2(x4,x5);
        g_xx[p] = x0*x0+x1*x1+x2*x2+x3*x3+x4*x4+x5*x5;
    }
    int o = t & 63;
    int pbase = blockIdx.x*256;
    for (int pi = (t>>6); pi < 256; pi += 4){
        int pp = pbase + pi;
        int bb = pp >> 12, nn = pp & 4095;
        const float* xp = x + bb*6*N_ + nn;
        float y0=xp[0], y1=xp[N_], y2=xp[2*N_], y3=xp[3*N_], y4=xp[4*N_], y5=xp[5*N_];
        const float* A = wa + o*6;
        const float* D = wd + o*6;
        g_nb[pp*64+o] = y0*A[0]+y1*A[1]+y2*A[2]+y3*A[3]+y4*A[4]+y5*A[5];
        g_cc[pp*64+o] = y0*D[0]+y1*D[1]+y2*D[2]+y3*D[3]+y4*D[4]+y5*D[5];
    }
}

// ---------------- kernel: KNN top-20 (4 queries/warp, short insert chain) -------
// grid = B_*64 blocks, 512 threads (16 warps). Warp handles 4 queries together.
__global__ void __launch_bounds__(512) k_knn(){
    int b   = blockIdx.x >> 6;
    int sec = blockIdx.x & 63;
    int w    = threadIdx.x >> 5;
    int lane = threadIdx.x & 31;
    int base = b*N_;
    const float2* xp0 = g_xp + base;
    const float2* xp1 = g_xp + PTS + base;
    const float2* xp2 = g_xp + 2*PTS + base;
    const float*  xxp = g_xx + base;

    int n0 = sec*64 + w*4;
    float q[4][6]; float lv[4]; int li[4]; float minv[4];
    #pragma unroll
    for (int j=0;j<4;j++){
        float2 a = xp0[n0+j], c = xp1[n0+j], e = xp2[n0+j];
        q[j][0]=a.x; q[j][1]=a.y; q[j][2]=c.x; q[j][3]=c.y; q[j][4]=e.x; q[j][5]=e.y;
        lv[j] = -3.4e38f; li[j] = 0; minv[j] = -3.4e38f;
    }

    for (int mb = 0; mb < N_; mb += 32){
        int m = mb + lane;
        float2 a = xp0[m], c = xp1[m], e = xp2[m];
        float xxm = xxp[m];
        float v[4];
        #pragma unroll
        for (int j=0;j<4;j++){
            float d = q[j][0]*a.x + q[j][1]*a.y + q[j][2]*c.x
                    + q[j][3]*c.y + q[j][4]*e.x + q[j][5]*e.y;
            v[j] = 2.f*d - xxm;
        }
        #pragma unroll
        for (int j=0;j<4;j++){
            unsigned cand = __ballot_sync(FULLMASK, v[j] > minv[j]);
            bool any = (cand != 0u);
            while (cand){
                int src = __ffs(cand)-1; cand &= cand-1;
                float cv = __shfl_sync(FULLMASK, v[j], src);
                float pv = __shfl_up_sync(FULLMASK, lv[j], 1);
                int   pq = __shfl_up_sync(FULLMASK, li[j], 1);
                unsigned lt = __ballot_sync(FULLMASK, lv[j] < cv) & 0xFFFFFu;
                if (lt){                              // warp-uniform
                    int pos = __ffs(lt)-1;            // in [0,19]
                    if (lane > pos && lane < KNN){ lv[j]=pv; li[j]=pq; }
                    if (lane == pos)             { lv[j]=cv; li[j]=mb+src; }
                }
            }
            if (any) minv[j] = __shfl_sync(FULLMASK, lv[j], 19);
        }
    }
    #pragma unroll
    for (int j=0;j<4;j++)
        if (lane < KNN) g_idx[(base + n0 + j)*KNN + lane] = li[j];
}

// ---------------- kernel: z1 channel stats + bn1 finalize (last block) ----------------
__global__ void __launch_bounds__(256) k_stats1(const float* __restrict__ ga,
                                                const float* __restrict__ be){
    int t = threadIdx.x, o = t & 63, grp = t >> 6;
    float s = 0.f, ss = 0.f;
    for (int pi = blockIdx.x*4 + grp; pi < PTS; pi += 4096){
        float ccv = g_cc[pi*64 + o];
        int bbase = (pi >> 12) << 12;
        const int* ip = g_idx + pi*KNN;
        #pragma unroll
        for (int k=0;k<KNN;k++){
            int r = ip[k];
            float v = g_nb[(bbase + r)*64 + o] + ccv;
            s += v; ss += v*v;
        }
    }
    __shared__ float sh[256], sh2[256];
    sh[t] = s; sh2[t] = ss;
    __syncthreads();
    if (t < 64){
        atomicAdd(&g_s[t],    sh[t]+sh[t+64]+sh[t+128]+sh[t+192]);
        atomicAdd(&g_s[64+t], sh2[t]+sh2[t+64]+sh2[t+128]+sh2[t+192]);
    }
    __threadfence();
    __syncthreads();
    __shared__ int lastb;
    if (t == 0) lastb = (atomicAdd(&g_c0, 1) == (int)gridDim.x - 1);
    __syncthreads();
    if (lastb){
        if (t < 64){
            float cnt = (float)(PTS*KNN);
            float m = g_s[t]/cnt;
            float var = g_s[64+t]/cnt - m*m;
            float a = ga[t]*rsqrtf(var + 1e-5f);
            g_ab[t]    = a;
            g_ab[64+t] = be[t] - m*a;
        }
        if (t == 0) g_c0 = 0;
    }
}

// ---------------- conv2: 2 ch/thread, double-buffered 4-point phases ----------------
// grid 2048 x 128: t = (khalf<<6) | cpair. Thread owns channels 2cp,2cp+1 for k-half kh.
__global__ void __launch_bounds__(128) k_conv2(const float* __restrict__ w2,
                                               const float* __restrict__ ga,
                                               const float* __restrict__ be){
    int t = threadIdx.x;
    int kh = t >> 6;          // k in [kh*10, kh*10+10)
    int cp = t & 63;          // channel pair -> channels 2cp, 2cp+1
    ull w0[32], w1[32];
    {
        const ulonglong2* wr0 = (const ulonglong2*)(w2 + (2*cp)*64);
        const ulonglong2* wr1 = (const ulonglong2*)(w2 + (2*cp+1)*64);
        #pragma unroll
        for (int j=0;j<16;j++){
            ulonglong2 v0 = wr0[j]; w0[2*j]=v0.x; w0[2*j+1]=v0.y;
            ulonglong2 v1 = wr1[j]; w1[2*j]=v1.x; w1[2*j+1]=v1.y;
        }
    }
    __shared__ __align__(16) float h1[2][4][20*64];   // 40KB double buffer
    __shared__ float mx1[2][4][128];                  // kh1 partial maxes, 4KB
    float a1 = g_ab[cp], b1 = g_ab[64+cp];
    float s0=0.f, ss0=0.f, s1=0.f, ss1=0.f;
    float m0r[4], m1r[4];

    int p0 = blockIdx.x*16;
    // prologue gather: phase 0 -> buffer 0
    #pragma unroll
    for (int pp=0;pp<4;pp++){
        int pi = p0 + pp;
        int bbase = (pi >> 12) << 12;
        float ccv = g_cc[pi*64 + cp];
        const int* ip = g_idx + pi*KNN;
        #pragma unroll
        for (int kk=0;kk<10;kk++){
            int k = kh*10 + kk;
            int r = ip[k];
            h1[0][pp][k*64 + cp] = lrelu(fmaf(a1, g_nb[(bbase + r)*64 + cp] + ccv, b1));
        }
    }
    __syncthreads();

    for (int ph = 0; ph < 4; ++ph){
        int par = ph & 1;
        if (ph < 3){
            int pb = p0 + (ph+1)*4;
            #pragma unroll
            for (int pp=0;pp<4;pp++){
                int pi = pb + pp;
                int bbase = (pi >> 12) << 12;
                float ccv = g_cc[pi*64 + cp];
                const int* ip = g_idx + pi*KNN;
                #pragma unroll
                for (int kk=0;kk<10;kk++){
                    int k = kh*10 + kk;
                    int r = ip[k];
                    h1[par^1][pp][k*64 + cp] = lrelu(fmaf(a1, g_nb[(bbase + r)*64 + cp] + ccv, b1));
                }
            }
        }
        // compute on h1[par]
        #pragma unroll
        for (int pp=0;pp<4;pp++){
            float m0 = -3.4e38f, m1 = -3.4e38f;
            for (int kk=0;kk<10;kk++){
                int k = kh*10 + kk;
                const ulonglong2* hp = (const ulonglong2*)(h1[par][pp] + k*64);
                ull A0=0ull, B0=0ull, A1=0ull, B1=0ull;
                #pragma unroll
                for (int j=0;j<16;j++){
                    ulonglong2 h = hp[j];
                    ffma2(A0, w0[2*j],   h.x);
                    ffma2(B0, w0[2*j+1], h.y);
                    ffma2(A1, w1[2*j],   h.x);
                    ffma2(B1, w1[2*j+1], h.y);
                }
                fadd2(A0, B0); fadd2(A1, B1);
                float z0 = f2lo(A0) + f2hi(A0);
                float z1 = f2lo(A1) + f2hi(A1);
                s0 += z0; ss0 += z0*z0; m0 = fmaxf(m0, z0);
                s1 += z1; ss1 += z1*z1; m1 = fmaxf(m1, z1);
            }
            if (kh){ mx1[par][pp][2*cp] = m0; mx1[par][pp][2*cp+1] = m1; }
            else   { m0r[pp] = m0; m1r[pp] = m1; }
        }
        __syncthreads();
        // combine & store this phase's maxes (mx1[par] stable until compute of ph+2)
        if (kh == 0){
            #pragma unroll
            for (int pp=0;pp<4;pp++){
                int pi = p0 + ph*4 + pp;
                float2 v;
                v.x = fmaxf(m0r[pp], mx1[par][pp][2*cp]);
                v.y = fmaxf(m1r[pp], mx1[par][pp][2*cp+1]);
                *(float2*)(g_m2 + pi*128 + 2*cp) = v;
            }
        }
    }
    atomicAdd(&g_s[128+2*cp],   s0);
    atomicAdd(&g_s[128+2*cp+1], s1);
    atomicAdd(&g_s[256+2*cp],   ss0);
    atomicAdd(&g_s[256+2*cp+1], ss1);
    __threadfence();
    __syncthreads();
    __shared__ int lastb;
    if (t == 0) lastb = (atomicAdd(&g_c1, 1) == (int)gridDim.x - 1);
    __syncthreads();
    if (lastb){
        float cnt = (float)(PTS*KNN);
        float m = g_s[128+t]/cnt;
        float var = g_s[256+t]/cnt - m*m;
        float a = ga[t]*rsqrtf(var + 1e-5f);
        g_ab[128+t] = a;
        g_ab[256+t] = be[t] - m*a;
        if (t == 0) g_c1 = 0;
    }
}

// ---------------- conv3: 2 ch/thread, K-quarter split, double-buffered --------------
// grid 512 = 16 chunks x 8 batches x 4 sections; 128 threads.
// t: kq=t&3 picks input quarter [kq*32, kq*32+32); p2=t>>2 -> channels chunk*64+2p2,+1.
__global__ void __launch_bounds__(128) k_conv3(const float* __restrict__ w3,
                                               const float* __restrict__ ga,
                                               const float* __restrict__ be){
    int t = threadIdx.x;
    int kq = t & 3;
    int p2 = t >> 2;               // 0..31
    int chunk = blockIdx.x & 15;
    int rem   = blockIdx.x >> 4;
    int bb    = rem & 7;
    int sec   = rem >> 3;          // 0..3
    int c0 = chunk*64 + 2*p2;

    ull w0[16], w1[16];
    {
        const ulonglong2* wr0 = (const ulonglong2*)(w3 + c0*128     + kq*32);
        const ulonglong2* wr1 = (const ulonglong2*)(w3 + (c0+1)*128 + kq*32);
        #pragma unroll
        for (int j=0;j<8;j++){
            ulonglong2 v0 = wr0[j]; w0[2*j]=v0.x; w0[2*j+1]=v0.y;
            ulonglong2 v1 = wr1[j]; w1[2*j]=v1.x; w1[2*j+1]=v1.y;
        }
    }
    __shared__ __align__(16) float h2[2][1024];   // 8KB double buffer (8 pts/phase)
    __shared__ float sab[128], sbb[128];
    sab[t] = g_ab[128+t]; sbb[t] = g_ab[256+t];
    __syncthreads();
    float s=0.f, ss=0.f, maxv=-3.4e38f;

    int pbase = (bb << 12) + sec*1024;
    // prologue gather
    #pragma unroll
    for (int i = t; i < 1024; i += 128){
        int ch = i & 127;
        h2[0][i] = lrelu(fmaf(sab[ch], g_m2[(pbase + (i>>7))*128 + ch], sbb[ch]));
    }
    __syncthreads();

    for (int ph = 0; ph < 128; ++ph){
        int par = ph & 1;
        if (ph < 127){
            int pb = pbase + (ph+1)*8;
            #pragma unroll
            for (int i = t; i < 1024; i += 128){
                int ch = i & 127;
                h2[par^1][i] = lrelu(fmaf(sab[ch], g_m2[(pb + (i>>7))*128 + ch], sbb[ch]));
            }
        }
        #pragma unroll
        for (int pl=0; pl<8; ++pl){
            const ulonglong2* hp = (const ulonglong2*)(h2[par] + pl*128 + kq*32);
            ull A0=0ull, B0=0ull, A1=0ull, B1=0ull;
            #pragma unroll
            for (int j=0;j<8;j++){
                ulonglong2 h = hp[j];
                ffma2(A0, w0[2*j],   h.x);
                ffma2(B0, w0[2*j+1], h.y);
                ffma2(A1, w1[2*j],   h.x);
                ffma2(B1, w1[2*j+1], h.y);
            }
            fadd2(A0, B0); fadd2(A1, B1);
            float z0p = f2lo(A0) + f2hi(A0);
            float z1p = f2lo(A1) + f2hi(A1);
            z0p += __shfl_xor_sync(FULLMASK, z0p, 1);
            z0p += __shfl_xor_sync(FULLMASK, z0p, 2);
            z1p += __shfl_xor_sync(FULLMASK, z1p, 1);
            z1p += __shfl_xor_sync(FULLMASK, z1p, 2);
            float z = (kq == 0) ? z0p : z1p;
            if (kq < 2){ s += z; ss += z*z; maxv = fmaxf(maxv, z); }
        }
        __syncthreads();
    }
    if (kq < 2){
        int ch = c0 + kq;
        atomicAdd(&g_s[384+ch],  s);
        atomicAdd(&g_s[1408+ch], ss);
        atomicMax(&g_z3e[bb*1024 + ch], fenc(maxv));
    }
    __threadfence();
    __syncthreads();
    __shared__ int lastb;
    if (t == 0) lastb = (atomicAdd(&g_c2, 1) == (int)gridDim.x - 1);
    __syncthreads();
    if (lastb){
        float cnt = (float)PTS;
        for (int c = t; c < 1024; c += 128){
            float m = g_s[384+c]/cnt;
            float var = g_s[1408+c]/cnt - m*m;
            float a = ga[c]*rsqrtf(var + 1e-5f);
            float bo = be[c] - m*a;
            #pragma unroll
            for (int b=0;b<B_;b++)
                g_g[b*1024+c] = lrelu(fmaf(a, fdec(g_z3e[b*1024+c]), bo));
        }
        if (t == 0) g_c2 = 0;
    }
}

// ---------------- kernel: fc1 + bn4 + lrelu ----------------
__global__ void __launch_bounds__(128) k_fc1(const float* __restrict__ fw,
                                             const float* __restrict__ g4g,
                                             const float* __restrict__ g4b){
    __shared__ float gs[B_*1024];
    int t = threadIdx.x;
    for (int i=t;i<B_*1024;i+=128) gs[i] = g_g[i];
    __syncthreads();
    int w = t >> 5, lane = t & 31;
    for (int jj=0;jj<2;jj++){
        int j = blockIdx.x*8 + w*2 + jj;
        const float* wrow = fw + j*1024;
        float acc[8] = {0,0,0,0,0,0,0,0};
        for (int c=lane;c<1024;c+=32){
            float wv = wrow[c];
            #pragma unroll
            for (int b=0;b<8;b++) acc[b] += gs[b*1024+c]*wv;
        }
        #pragma unroll
        for (int b=0;b<8;b++){
            #pragma unroll
            for (int off=16;off;off>>=1) acc[b] += __shfl_xor_sync(FULLMASK, acc[b], off);
        }
        if (lane == 0){
            float m=0.f;
            #pragma unroll
            for (int b=0;b<8;b++) m += acc[b];
            m *= 0.125f;
            float var=0.f;
            #pragma unroll
            for (int b=0;b<8;b++){ float d = acc[b]-m; var += d*d; }
            var *= 0.125f;
            float a = g4g[j]*rsqrtf(var + 1e-5f);
            float bo = g4b[j] - m*a;
            #pragma unroll
            for (int b=0;b<8;b++) g_g4[b*512+j] = lrelu(a*acc[b] + bo);
        }
    }
}

// ---------------- kernel: fc2+bn5+lrelu, fc3/fc4 -> mat/bias ----------------
__global__ void __launch_bounds__(256) k_head(const float* __restrict__ f2w,
        const float* __restrict__ g5g, const float* __restrict__ g5b,
        const float* __restrict__ f3w, const float* __restrict__ f3b,
        const float* __restrict__ f4w, const float* __restrict__ f4b){
    __shared__ float g4s[B_*512];
    __shared__ float g5s[B_*256];
    int t = threadIdx.x, w = t >> 5, lane = t & 31;
    for (int i=t;i<B_*512;i+=256) g4s[i] = g_g4[i];
    __syncthreads();
    for (int jj=0;jj<32;jj++){
        int j = w*32 + jj;
        const float* wrow = f2w + j*512;
        float acc[8] = {0,0,0,0,0,0,0,0};
        for (int c=lane;c<512;c+=32){
            float wv = wrow[c];
            #pragma unroll
            for (int b=0;b<8;b++) acc[b] += g4s[b*512+c]*wv;
        }
        #pragma unroll
        for (int b=0;b<8;b++){
            #pragma unroll
            for (int off=16;off;off>>=1) acc[b] += __shfl_xor_sync(FULLMASK, acc[b], off);
        }
        if (lane == 0){
            float m=0.f;
            #pragma unroll
            for (int b=0;b<8;b++) m += acc[b];
            m *= 0.125f;
            float var=0.f;
            #pragma unroll
            for (int b=0;b<8;b++){ float d = acc[b]-m; var += d*d; }
            var *= 0.125f;
            float a = g5g[j]*rsqrtf(var + 1e-5f);
            float bo = g5b[j] - m*a;
            #pragma unroll
            for (int b=0;b<8;b++) g5s[b*256+j] = lrelu(a*acc[b] + bo);
        }
    }
    __syncthreads();
    for (int i=0;i<12;i++){
        int task = w*12 + i;           // 0..95
        int b = task / 12, jo = task % 12;
        const float* wrow = (jo < 9) ? (f3w + jo*256) : (f4w + (jo-9)*256);
        float acc = 0.f;
        for (int c=lane;c<256;c+=32) acc += g5s[b*256+c]*wrow[c];
        #pragma unroll
        for (int off=16;off;off>>=1) acc += __shfl_xor_sync(FULLMASK, acc, off);
        if (lane == 0){
            if (jo < 9){
                int r = jo/3, cc = jo%3;
                g_mat[b*9+jo] = acc + f3b[jo] + (r==cc ? 1.f : 0.f);
            } else {
                g_bias[b*3 + (jo-9)] = acc + f4b[jo-9];
            }
        }
    }
}

// ---------------- kernel: apply 3x3 transform ----------------
__global__ void k_out(const float* __restrict__ x, float* __restrict__ out){
    int p = blockIdx.x*1024 + threadIdx.x;   // 32 blocks x 1024 = 32768
    int b = p >> 12, n = p & 4095;
    const float* xb = x + b*6*N_ + n;
    float x0 = xb[0], x1 = xb[N_], x2 = xb[2*N_];
    const float* M  = g_mat + b*9;
    const float* Bi = g_bias + b*3;
    float* ob = out + b*3*N_ + n;
    ob[0]    = x0*M[0] + x1*M[3] + x2*M[6] + Bi[0];
    ob[N_]   = x0*M[1] + x1*M[4] + x2*M[7] + Bi[1];
    ob[2*N_] = x0*M[2] + x1*M[5] + x2*M[8] + Bi[2];
}

// ---------------- launch ----------------
extern "C" void kernel_launch(void* const* d_in, const int* in_sizes, int n_in,
                              void* d_out, int out_size){
    const float* x     = (const float*)d_in[0];
    const float* w1    = (const float*)d_in[1];
    const float* bn1g  = (const float*)d_in[2];
    const float* bn1b  = (const float*)d_in[3];
    const float* w2    = (const float*)d_in[4];
    const float* bn2g  = (const float*)d_in[5];
    const float* bn2b  = (const float*)d_in[6];
    const float* w3    = (const float*)d_in[7];
    const float* bn3g  = (const float*)d_in[8];
    const float* bn3b  = (const float*)d_in[9];
    const float* fc1w  = (const float*)d_in[10];
    const float* bn4g  = (const float*)d_in[11];
    const float* bn4b  = (const float*)d_in[12];
    const float* fc2w  = (const float*)d_in[13];
    const float* bn5g  = (const float*)d_in[14];
    const float* bn5b  = (const float*)d_in[15];
    const float* fc3w  = (const float*)d_in[16];
    const float* fc3b  = (const float*)d_in[17];
    const float* fc4w  = (const float*)d_in[18];
    const float* fc4b  = (const float*)d_in[19];
    float* out = (float*)d_out;

    k_prep  <<<128, 256>>>(x, w1);       // 1
    k_zero2 <<<1, 256>>>();              // 2
    k_nop   <<<1, 32>>>();               // 3
    k_knn   <<<B_*64, 512>>>();          // 4  <- ncu capture slot
    k_stats1<<<1024, 256>>>(bn1g, bn1b); // 5
    k_conv2 <<<2048, 128>>>(w2, bn2g, bn2b);
    k_conv3 <<<512, 128>>>(w3, bn3g, bn3b);
    k_fc1   <<<64, 128>>>(fc1w, bn4g, bn4b);
    k_head  <<<1, 256>>>(fc2w, bn5g, bn5b, fc3w, fc3b, fc4w, fc4b);
    k_out   <<<32, 1024>>>(x, out);
}

// round 7
// speedup vs baseline: 1.7894x; 1.7894x over previous
#include <cuda_runtime.h>

#define B_ 8
#define N_ 4096
#define KNN 20
#define PTS (B_*N_)
#define FULLMASK 0xFFFFFFFFu
typedef unsigned long long ull;

// ---------------- static device scratch (no allocation) ----------------
__device__ float2   g_xp[3*PTS];     // SoA channel pairs per point
__device__ float    g_xx[PTS];       // squared norms
__device__ float    g_nb[PTS*64];    // x . W1[:, :6]^T
__device__ float    g_cc[PTS*64];    // x . (W1[:,6:]-W1[:, :6])^T
__device__ int      g_idx[PTS*KNN];  // knn indices (within batch)
__device__ float    g_m2[PTS*128];   // max_k z2 (pre-BN)
__device__ float    g_s[2432];       // stats: s1[64] ss1[64] s2[128] ss2[128] s3[1024] ss3[1024]
__device__ float    g_ab[384];       // BN affine: a1[64] b1[64] a2[128] b2[128]
__device__ unsigned g_z3e[B_*1024];  // encoded max_n z3
__device__ float    g_g[B_*1024];    // global feature (after bn3+lrelu)
__device__ float    g_g4[B_*512];    // after fc1+bn4+lrelu
__device__ float    g_mat[B_*9];
__device__ float    g_bias[B_*3];
__device__ int      g_c0 = 0;        // stats1 completion counter
__device__ int      g_c1 = 0;        // conv2 completion counter
__device__ int      g_c2 = 0;        // conv3 completion counter

__device__ __forceinline__ float lrelu(float x){ return x >= 0.f ? x : 0.2f*x; }
__device__ __forceinline__ unsigned fenc(float f){
    unsigned u = __float_as_uint(f);
    return (u & 0x80000000u) ? ~u : (u | 0x80000000u);
}
__device__ __forceinline__ float fdec(unsigned u){
    u = (u & 0x80000000u) ? (u & 0x7FFFFFFFu) : ~u;
    return __uint_as_float(u);
}
__device__ __forceinline__ float f2lo(ull v){ return __uint_as_float((unsigned)v); }
__device__ __forceinline__ float f2hi(ull v){ return __uint_as_float((unsigned)(v>>32)); }
__device__ __forceinline__ void ffma2(ull& d, ull a, ull b){
    asm("fma.rn.f32x2 %0, %1, %2, %0;" : "+l"(d) : "l"(a), "l"(b));
}
__device__ __forceinline__ void fadd2(ull& d, ull b){
    asm("add.rn.f32x2 %0, %0, %1;" : "+l"(d) : "l"(b));
}

// ---------------- kernel 0: zero + transpose + norms + conv1 precompute ----------------
__global__ void k_prep(const float* __restrict__ x, const float* __restrict__ w1){
    __shared__ float wa[384], wd[384];
    int t = threadIdx.x;
    if (blockIdx.x == 0){
        for (int i = t; i < 2432; i += 256) g_s[i] = 0.f;
        for (int i = t; i < B_*1024; i += 256) g_z3e[i] = 0u;
    }
    for (int i = t; i < 384; i += 256){
        int o = i/6, c = i%6;
        float a = w1[o*12 + c];
        wa[i] = a;
        wd[i] = w1[o*12 + 6 + c] - a;
    }
    __syncthreads();

    int p = blockIdx.x*256 + t;            // 128 blocks x 256 = 32768
    {
        int b = p >> 12, n = p & 4095;
        const float* xb = x + b*6*N_ + n;
        float x0=xb[0], x1=xb[N_], x2=xb[2*N_], x3=xb[3*N_], x4=xb[4*N_], x5=xb[5*N_];
        g_xp[p]       = make_float2(x0,x1);
        g_xp[PTS+p]   = make_float2(x2,x3);
        g_xp[2*PTS+p] = make_float2(x4,x5);
        g_xx[p] = x0*x0+x1*x1+x2*x2+x3*x3+x4*x4+x5*x5;
    }
    int o = t & 63;
    int pbase = blockIdx.x*256;
    for (int pi = (t>>6); pi < 256; pi += 4){
        int pp = pbase + pi;
        int bb = pp >> 12, nn = pp & 4095;
        const float* xp = x + bb*6*N_ + nn;
        float y0=xp[0], y1=xp[N_], y2=xp[2*N_], y3=xp[3*N_], y4=xp[4*N_], y5=xp[5*N_];
        const float* A = wa + o*6;
        const float* D = wd + o*6;
        g_nb[pp*64+o] = y0*A[0]+y1*A[1]+y2*A[2]+y3*A[3]+y4*A[4]+y5*A[5];
        g_cc[pp*64+o] = y0*D[0]+y1*D[1]+y2*D[2]+y3*D[3]+y4*D[4]+y5*D[5];
    }
}

// ---------------- kernel 1: KNN top-20 (4 queries/warp, short insert chain) -------
// grid = B_*64 blocks, 512 threads (16 warps). Warp handles 4 queries together.
__global__ void __launch_bounds__(512) k_knn(){
    int b   = blockIdx.x >> 6;
    int sec = blockIdx.x & 63;
    int w    = threadIdx.x >> 5;
    int lane = threadIdx.x & 31;
    int base = b*N_;
    const float2* xp0 = g_xp + base;
    const float2* xp1 = g_xp + PTS + base;
    const float2* xp2 = g_xp + 2*PTS + base;
    const float*  xxp = g_xx + base;

    int n0 = sec*64 + w*4;
    float q[4][6]; float lv[4]; int li[4]; float minv[4];
    #pragma unroll
    for (int j=0;j<4;j++){
        float2 a = xp0[n0+j], c = xp1[n0+j], e = xp2[n0+j];
        q[j][0]=a.x; q[j][1]=a.y; q[j][2]=c.x; q[j][3]=c.y; q[j][4]=e.x; q[j][5]=e.y;
        lv[j] = -3.4e38f; li[j] = 0; minv[j] = -3.4e38f;
    }

    for (int mb = 0; mb < N_; mb += 32){
        int m = mb + lane;
        float2 a = xp0[m], c = xp1[m], e = xp2[m];
        float xxm = xxp[m];
        float v[4];
        #pragma unroll
        for (int j=0;j<4;j++){
            float d = q[j][0]*a.x + q[j][1]*a.y + q[j][2]*c.x
                    + q[j][3]*c.y + q[j][4]*e.x + q[j][5]*e.y;
            v[j] = 2.f*d - xxm;
        }
        #pragma unroll
        for (int j=0;j<4;j++){
            unsigned cand = __ballot_sync(FULLMASK, v[j] > minv[j]);
            bool any = (cand != 0u);
            while (cand){
                int src = __ffs(cand)-1; cand &= cand-1;
                float cv = __shfl_sync(FULLMASK, v[j], src);
                float pv = __shfl_up_sync(FULLMASK, lv[j], 1);
                int   pq = __shfl_up_sync(FULLMASK, li[j], 1);
                unsigned lt = __ballot_sync(FULLMASK, lv[j] < cv) & 0xFFFFFu;
                if (lt){                              // warp-uniform
                    int pos = __ffs(lt)-1;            // in [0,19]
                    if (lane > pos && lane < KNN){ lv[j]=pv; li[j]=pq; }
                    if (lane == pos)             { lv[j]=cv; li[j]=mb+src; }
                }
            }
            if (any) minv[j] = __shfl_sync(FULLMASK, lv[j], 19);
        }
    }
    #pragma unroll
    for (int j=0;j<4;j++)
        if (lane < KNN) g_idx[(base + n0 + j)*KNN + lane] = li[j];
}

// ---------------- kernel 2: z1 channel stats + bn1 finalize (last block) ----------------
__global__ void __launch_bounds__(256) k_stats1(const float* __restrict__ ga,
                                                const float* __restrict__ be){
    int t = threadIdx.x, o = t & 63, grp = t >> 6;
    float s = 0.f, ss = 0.f;
    for (int pi = blockIdx.x*4 + grp; pi < PTS; pi += 4096){
        float ccv = g_cc[pi*64 + o];
        int bbase = (pi >> 12) << 12;
        const int* ip = g_idx + pi*KNN;
        #pragma unroll
        for (int k=0;k<KNN;k++){
            int r = ip[k];
            float v = g_nb[(bbase + r)*64 + o] + ccv;
            s += v; ss += v*v;
        }
    }
    __shared__ float sh[256], sh2[256];
    sh[t] = s; sh2[t] = ss;
    __syncthreads();
    if (t < 64){
        atomicAdd(&g_s[t],    sh[t]+sh[t+64]+sh[t+128]+sh[t+192]);
        atomicAdd(&g_s[64+t], sh2[t]+sh2[t+64]+sh2[t+128]+sh2[t+192]);
    }
    __threadfence();
    __syncthreads();
    __shared__ int lastb;
    if (t == 0) lastb = (atomicAdd(&g_c0, 1) == (int)gridDim.x - 1);
    __syncthreads();
    if (lastb){
        if (t < 64){
            float cnt = (float)(PTS*KNN);
            float m = g_s[t]/cnt;
            float var = g_s[64+t]/cnt - m*m;
            float a = ga[t]*rsqrtf(var + 1e-5f);
            g_ab[t]    = a;
            g_ab[64+t] = be[t] - m*a;
        }
        if (t == 0) g_c0 = 0;
    }
}

// ---------------- kernel 3: conv2 (2 ch/thread, 4-point phases) + stats + max + bn2 ----
// grid 2048 x 128: t = (khalf<<6) | cpair. Thread owns channels 2cp,2cp+1 for k-half kh.
__global__ void __launch_bounds__(128) k_conv2(const float* __restrict__ w2,
                                               const float* __restrict__ ga,
                                               const float* __restrict__ be){
    int t = threadIdx.x;
    int kh = t >> 6;          // k in [kh*10, kh*10+10)
    int cp = t & 63;          // channel pair -> channels 2cp, 2cp+1
    ull w0[32], w1[32];
    {
        const ulonglong2* wr0 = (const ulonglong2*)(w2 + (2*cp)*64);
        const ulonglong2* wr1 = (const ulonglong2*)(w2 + (2*cp+1)*64);
        #pragma unroll
        for (int j=0;j<16;j++){
            ulonglong2 v0 = wr0[j]; w0[2*j]=v0.x; w0[2*j+1]=v0.y;
            ulonglong2 v1 = wr1[j]; w1[2*j]=v1.x; w1[2*j+1]=v1.y;
        }
    }
    __shared__ __align__(16) float h1[4][20*64];   // 20KB
    __shared__ float mx[2][4][128];                // partial maxes per k-half
    float a1 = g_ab[cp], b1 = g_ab[64+cp];
    float s0=0.f, ss0=0.f, s1=0.f, ss1=0.f;

    int p0 = blockIdx.x*16;
    for (int ph = 0; ph < 4; ++ph){
        int pb = p0 + ph*4;
        __syncthreads();
        // combine & store previous phase's maxes (kh==0 threads)
        if (ph > 0 && kh == 0){
            #pragma unroll
            for (int pp=0;pp<4;pp++){
                int pi = pb - 4 + pp;
                float2 v;
                v.x = fmaxf(mx[0][pp][2*cp],   mx[1][pp][2*cp]);
                v.y = fmaxf(mx[0][pp][2*cp+1], mx[1][pp][2*cp+1]);
                *(float2*)(g_m2 + pi*128 + 2*cp) = v;
            }
        }
        // gather 4 points (40 independent-ish loads per thread)
        #pragma unroll
        for (int pp=0;pp<4;pp++){
            int pi = pb + pp;
            int bbase = (pi >> 12) << 12;
            float ccv = g_cc[pi*64 + cp];
            const int* ip = g_idx + pi*KNN;
            #pragma unroll
            for (int kk=0;kk<10;kk++){
                int k = kh*10 + kk;
                int r = ip[k];
                h1[pp][k*64 + cp] = lrelu(fmaf(a1, g_nb[(bbase + r)*64 + cp] + ccv, b1));
            }
        }
        __syncthreads();
        // compute 4 points x 10 k
        #pragma unroll
        for (int pp=0;pp<4;pp++){
            float m0 = -3.4e38f, m1 = -3.4e38f;
            for (int kk=0;kk<10;kk++){
                int k = kh*10 + kk;
                const ulonglong2* hp = (const ulonglong2*)(h1[pp] + k*64);
                ull A0=0ull, B0=0ull, A1=0ull, B1=0ull;
                #pragma unroll
                for (int j=0;j<16;j++){
                    ulonglong2 h = hp[j];
                    ffma2(A0, w0[2*j],   h.x);
                    ffma2(B0, w0[2*j+1], h.y);
                    ffma2(A1, w1[2*j],   h.x);
                    ffma2(B1, w1[2*j+1], h.y);
                }
                fadd2(A0, B0); fadd2(A1, B1);
                float z0 = f2lo(A0) + f2hi(A0);
                float z1 = f2lo(A1) + f2hi(A1);
                s0 += z0; ss0 += z0*z0; m0 = fmaxf(m0, z0);
                s1 += z1; ss1 += z1*z1; m1 = fmaxf(m1, z1);
            }
            mx[kh][pp][2*cp]   = m0;
            mx[kh][pp][2*cp+1] = m1;
        }
    }
    __syncthreads();
    if (kh == 0){
        #pragma unroll
        for (int pp=0;pp<4;pp++){
            int pi = p0 + 12 + pp;
            float2 v;
            v.x = fmaxf(mx[0][pp][2*cp],   mx[1][pp][2*cp]);
            v.y = fmaxf(mx[0][pp][2*cp+1], mx[1][pp][2*cp+1]);
            *(float2*)(g_m2 + pi*128 + 2*cp) = v;
        }
    }
    atomicAdd(&g_s[128+2*cp],   s0);
    atomicAdd(&g_s[128+2*cp+1], s1);
    atomicAdd(&g_s[256+2*cp],   ss0);
    atomicAdd(&g_s[256+2*cp+1], ss1);
    __threadfence();
    __syncthreads();
    __shared__ int lastb;
    if (t == 0) lastb = (atomicAdd(&g_c1, 1) == (int)gridDim.x - 1);
    __syncthreads();
    if (lastb){
        float cnt = (float)(PTS*KNN);
        float m = g_s[128+t]/cnt;
        float var = g_s[256+t]/cnt - m*m;
        float a = ga[t]*rsqrtf(var + 1e-5f);
        g_ab[128+t] = a;
        g_ab[256+t] = be[t] - m*a;
        if (t == 0) g_c1 = 0;
    }
}

// ---------------- kernel 4: conv3 (2 ch/thread, K split across lane pairs) ----------
// grid 512 = 8 chunks x 8 batches x 8 sections; 128 threads.
__global__ void __launch_bounds__(128) k_conv3(const float* __restrict__ w3,
                                               const float* __restrict__ ga,
                                               const float* __restrict__ be){
    int t = threadIdx.x;
    int chunk = blockIdx.x & 7;
    int rem   = blockIdx.x >> 3;
    int bb    = rem & 7;
    int sec   = rem >> 3;          // 0..7
    int kh = t & 1;
    int p2 = t >> 1;               // 0..63
    int c0 = chunk*128 + 2*p2;

    ull w0[32], w1[32];
    {
        const ulonglong2* wr0 = (const ulonglong2*)(w3 + c0*128     + kh*64);
        const ulonglong2* wr1 = (const ulonglong2*)(w3 + (c0+1)*128 + kh*64);
        #pragma unroll
        for (int j=0;j<16;j++){
            ulonglong2 v0 = wr0[j]; w0[2*j]=v0.x; w0[2*j+1]=v0.y;
            ulonglong2 v1 = wr1[j]; w1[2*j]=v1.x; w1[2*j+1]=v1.y;
        }
    }
    __shared__ __align__(16) float h2[8*128];
    __shared__ float sab[128], sbb[128];
    if (t < 128){ sab[t] = g_ab[128+t]; sbb[t] = g_ab[256+t]; }
    float s=0.f, ss=0.f, maxv=-3.4e38f;

    int pbase = (bb << 12) + sec*512;
    for (int pp = 0; pp < 512; pp += 8){
        __syncthreads();
        #pragma unroll
        for (int i = t; i < 8*128; i += 128){
            int pl = i >> 7, ch = i & 127;
            h2[i] = lrelu(fmaf(sab[ch], g_m2[(pbase+pp+pl)*128 + ch], sbb[ch]));
        }
        __syncthreads();
        #pragma unroll 2
        for (int pl=0; pl<8; ++pl){
            const ulonglong2* hp = (const ulonglong2*)(h2 + pl*128 + kh*64);
            ull A0=0ull, B0=0ull, A1=0ull, B1=0ull;
            #pragma unroll
            for (int j=0;j<16;j++){
                ulonglong2 h = hp[j];
                ffma2(A0, w0[2*j],   h.x);
                ffma2(B0, w0[2*j+1], h.y);
                ffma2(A1, w1[2*j],   h.x);
                ffma2(B1, w1[2*j+1], h.y);
            }
            fadd2(A0, B0); fadd2(A1, B1);
            float z0p = f2lo(A0) + f2hi(A0);
            float z1p = f2lo(A1) + f2hi(A1);
            float z0 = z0p + __shfl_xor_sync(FULLMASK, z0p, 1);
            float z1 = z1p + __shfl_xor_sync(FULLMASK, z1p, 1);
            float z = kh ? z1 : z0;
            s += z; ss += z*z;
            maxv = fmaxf(maxv, z);
        }
    }
    int ch = chunk*128 + t;        // == c0 + kh
    atomicAdd(&g_s[384+ch],  s);
    atomicAdd(&g_s[1408+ch], ss);
    atomicMax(&g_z3e[bb*1024 + ch], fenc(maxv));
    __threadfence();
    __syncthreads();
    __shared__ int lastb;
    if (t == 0) lastb = (atomicAdd(&g_c2, 1) == (int)gridDim.x - 1);
    __syncthreads();
    if (lastb){
        float cnt = (float)PTS;
        for (int c = t; c < 1024; c += 128){
            float m = g_s[384+c]/cnt;
            float var = g_s[1408+c]/cnt - m*m;
            float a = ga[c]*rsqrtf(var + 1e-5f);
            float bo = be[c] - m*a;
            #pragma unroll
            for (int b=0;b<B_;b++)
                g_g[b*1024+c] = lrelu(fmaf(a, fdec(g_z3e[b*1024+c]), bo));
        }
        if (t == 0) g_c2 = 0;
    }
}

// ---------------- kernel 5: fc1 + bn4 + lrelu ----------------
__global__ void __launch_bounds__(128) k_fc1(const float* __restrict__ fw,
                                             const float* __restrict__ g4g,
                                             const float* __restrict__ g4b){
    __shared__ float gs[B_*1024];
    int t = threadIdx.x;
    for (int i=t;i<B_*1024;i+=128) gs[i] = g_g[i];
    __syncthreads();
    int w = t >> 5, lane = t & 31;
    for (int jj=0;jj<2;jj++){
        int j = blockIdx.x*8 + w*2 + jj;
        const float* wrow = fw + j*1024;
        float acc[8] = {0,0,0,0,0,0,0,0};
        for (int c=lane;c<1024;c+=32){
            float wv = wrow[c];
            #pragma unroll
            for (int b=0;b<8;b++) acc[b] += gs[b*1024+c]*wv;
        }
        #pragma unroll
        for (int b=0;b<8;b++){
            #pragma unroll
            for (int off=16;off;off>>=1) acc[b] += __shfl_xor_sync(FULLMASK, acc[b], off);
        }
        if (lane == 0){
            float m=0.f;
            #pragma unroll
            for (int b=0;b<8;b++) m += acc[b];
            m *= 0.125f;
            float var=0.f;
            #pragma unroll
            for (int b=0;b<8;b++){ float d = acc[b]-m; var += d*d; }
            var *= 0.125f;
            float a = g4g[j]*rsqrtf(var + 1e-5f);
            float bo = g4b[j] - m*a;
            #pragma unroll
            for (int b=0;b<8;b++) g_g4[b*512+j] = lrelu(a*acc[b] + bo);
        }
    }
}

// ---------------- kernel 6: fc2+bn5+lrelu, fc3/fc4 -> mat/bias ----------------
__global__ void __launch_bounds__(256) k_head(const float* __restrict__ f2w,
        const float* __restrict__ g5g, const float* __restrict__ g5b,
        const float* __restrict__ f3w, const float* __restrict__ f3b,
        const float* __restrict__ f4w, const float* __restrict__ f4b){
    __shared__ float g4s[B_*512];
    __shared__ float g5s[B_*256];
    int t = threadIdx.x, w = t >> 5, lane = t & 31;
    for (int i=t;i<B_*512;i+=256) g4s[i] = g_g4[i];
    __syncthreads();
    for (int jj=0;jj<32;jj++){
        int j = w*32 + jj;
        const float* wrow = f2w + j*512;
        float acc[8] = {0,0,0,0,0,0,0,0};
        for (int c=lane;c<512;c+=32){
            float wv = wrow[c];
            #pragma unroll
            for (int b=0;b<8;b++) acc[b] += g4s[b*512+c]*wv;
        }
        #pragma unroll
        for (int b=0;b<8;b++){
            #pragma unroll
            for (int off=16;off;off>>=1) acc[b] += __shfl_xor_sync(FULLMASK, acc[b], off);
        }
        if (lane == 0){
            float m=0.f;
            #pragma unroll
            for (int b=0;b<8;b++) m += acc[b];
            m *= 0.125f;
            float var=0.f;
            #pragma unroll
            for (int b=0;b<8;b++){ float d = acc[b]-m; var += d*d; }
            var *= 0.125f;
            float a = g5g[j]*rsqrtf(var + 1e-5f);
            float bo = g5b[j] - m*a;
            #pragma unroll
            for (int b=0;b<8;b++) g5s[b*256+j] = lrelu(a*acc[b] + bo);
        }
    }
    __syncthreads();
    for (int i=0;i<12;i++){
        int task = w*12 + i;           // 0..95
        int b = task / 12, jo = task % 12;
        const float* wrow = (jo < 9) ? (f3w + jo*256) : (f4w + (jo-9)*256);
        float acc = 0.f;
        for (int c=lane;c<256;c+=32) acc += g5s[b*256+c]*wrow[c];
        #pragma unroll
        for (int off=16;off;off>>=1) acc += __shfl_xor_sync(FULLMASK, acc, off);
        if (lane == 0){
            if (jo < 9){
                int r = jo/3, cc = jo%3;
                g_mat[b*9+jo] = acc + f3b[jo] + (r==cc ? 1.f : 0.f);
            } else {
                g_bias[b*3 + (jo-9)] = acc + f4b[jo-9];
            }
        }
    }
}

// ---------------- kernel 7: apply 3x3 transform ----------------
__global__ void k_out(const float* __restrict__ x, float* __restrict__ out){
    int p = blockIdx.x*1024 + threadIdx.x;   // 32 blocks x 1024 = 32768
    int b = p >> 12, n = p & 4095;
    const float* xb = x + b*6*N_ + n;
    float x0 = xb[0], x1 = xb[N_], x2 = xb[2*N_];
    const float* M  = g_mat + b*9;
    const float* Bi = g_bias + b*3;
    float* ob = out + b*3*N_ + n;
    ob[0]    = x0*M[0] + x1*M[3] + x2*M[6] + Bi[0];
    ob[N_]   = x0*M[1] + x1*M[4] + x2*M[7] + Bi[1];
    ob[2*N_] = x0*M[2] + x1*M[5] + x2*M[8] + Bi[2];
}

// ---------------- launch ----------------
extern "C" void kernel_launch(void* const* d_in, const int* in_sizes, int n_in,
                              void* d_out, int out_size){
    const float* x     = (const float*)d_in[0];
    const float* w1    = (const float*)d_in[1];
    const float* bn1g  = (const float*)d_in[2];
    const float* bn1b  = (const float*)d_in[3];
    const float* w2    = (const float*)d_in[4];
    const float* bn2g  = (const float*)d_in[5];
    const float* bn2b  = (const float*)d_in[6];
    const float* w3    = (const float*)d_in[7];
    const float* bn3g  = (const float*)d_in[8];
    const float* bn3b  = (const float*)d_in[9];
    const float* fc1w  = (const float*)d_in[10];
    const float* bn4g  = (const float*)d_in[11];
    const float* bn4b  = (const float*)d_in[12];
    const float* fc2w  = (const float*)d_in[13];
    const float* bn5g  = (const float*)d_in[14];
    const float* bn5b  = (const float*)d_in[15];
    const float* fc3w  = (const float*)d_in[16];
    const float* fc3b  = (const float*)d_in[17];
    const float* fc4w  = (const float*)d_in[18];
    const float* fc4b  = (const float*)d_in[19];
    float* out = (float*)d_out;

    k_prep  <<<128, 256>>>(x, w1);          // 1
    k_knn   <<<B_*64, 512>>>();             // 2
    k_stats1<<<1024, 256>>>(bn1g, bn1b);    // 3
    k_conv2 <<<2048, 128>>>(w2, bn2g, bn2b);// 4  <- ncu capture slot
    k_conv3 <<<512, 128>>>(w3, bn3g, bn3b); // 5
    k_fc1   <<<64, 128>>>(fc1w, bn4g, bn4b);
    k_head  <<<1, 256>>>(fc2w, bn5g, bn5b, fc3w, fc3b, fc4w, fc4b);
    k_out   <<<32, 1024>>>(x, out);
}

// round 8
// speedup vs baseline: 1.9547x; 1.0923x over previous
#include <cuda_runtime.h>

#define B_ 8
#define N_ 4096
#define KNN 20
#define PTS (B_*N_)
#define FULLMASK 0xFFFFFFFFu
typedef unsigned long long ull;

// ---------------- static device scratch (no allocation) ----------------
__device__ float2   g_xp[3*PTS];     // SoA channel pairs per point
__device__ float    g_xx[PTS];       // squared norms
__device__ float    g_nb[PTS*64];    // x . W1[:, :6]^T
__device__ float    g_cc[PTS*64];    // x . (W1[:,6:]-W1[:, :6])^T
__device__ int      g_idx[PTS*KNN];  // knn indices (within batch)
__device__ float    g_m2[PTS*128];   // max_k z2 (pre-BN)
__device__ float    g_s[2432];       // stats: s1[64] ss1[64] s2[128] ss2[128] s3[1024] ss3[1024]
__device__ float    g_ab[384];       // BN affine: a1[64] b1[64] a2[128] b2[128]
__device__ unsigned g_z3e[B_*1024];  // encoded max_n z3
__device__ float    g_g[B_*1024];    // global feature (after bn3+lrelu)
__device__ float    g_g4[B_*512];    // after fc1+bn4+lrelu
__device__ float    g_mat[B_*9];
__device__ float    g_bias[B_*3];
__device__ int      g_c0 = 0;        // stats1 completion counter
__device__ int      g_c1 = 0;        // conv2 completion counter
__device__ int      g_c2 = 0;        // conv3 completion counter
// transposed weights for coalesced loads
__device__ ulonglong2 g_w2t[32][64];       // [j2][cp]  (j2<16 -> row 2cp, else row 2cp+1)
__device__ ulonglong2 g_w3t[8][32][128];   // [chunk][j2][t]

__device__ __forceinline__ float lrelu(float x){ return x >= 0.f ? x : 0.2f*x; }
__device__ __forceinline__ unsigned fenc(float f){
    unsigned u = __float_as_uint(f);
    return (u & 0x80000000u) ? ~u : (u | 0x80000000u);
}
__device__ __forceinline__ float fdec(unsigned u){
    u = (u & 0x80000000u) ? (u & 0x7FFFFFFFu) : ~u;
    return __uint_as_float(u);
}
__device__ __forceinline__ float f2lo(ull v){ return __uint_as_float((unsigned)v); }
__device__ __forceinline__ float f2hi(ull v){ return __uint_as_float((unsigned)(v>>32)); }
__device__ __forceinline__ void ffma2(ull& d, ull a, ull b){
    asm("fma.rn.f32x2 %0, %1, %2, %0;" : "+l"(d) : "l"(a), "l"(b));
}
__device__ __forceinline__ void fadd2(ull& d, ull b){
    asm("add.rn.f32x2 %0, %0, %1;" : "+l"(d) : "l"(b));
}

// ---------------- kernel 0: zero + transpose + norms + conv1 precompute + W transp ----
__global__ void k_prep(const float* __restrict__ x, const float* __restrict__ w1,
                       const float* __restrict__ w2, const float* __restrict__ w3){
    __shared__ float wa[384], wd[384];
    int t = threadIdx.x;
    if (blockIdx.x == 0){
        for (int i = t; i < 2432; i += 256) g_s[i] = 0.f;
        for (int i = t; i < B_*1024; i += 256) g_z3e[i] = 0u;
    }
    for (int i = t; i < 384; i += 256){
        int o = i/6, c = i%6;
        float a = w1[o*12 + c];
        wa[i] = a;
        wd[i] = w1[o*12 + 6 + c] - a;
    }
    __syncthreads();

    int p = blockIdx.x*256 + t;            // 128 blocks x 256 = 32768
    // W3 transpose: one element per thread
    {
        int chunk = p >> 12;
        int rem   = p & 4095;
        int j2 = rem >> 7;
        int tt = rem & 127;
        int kh = tt & 1, p2 = tt >> 1;
        int row = chunk*128 + 2*p2 + (j2 >= 16 ? 1 : 0);
        int j = j2 & 15;
        g_w3t[chunk][j2][tt] = ((const ulonglong2*)(w3 + row*128 + kh*64))[j];
    }
    // W2 transpose: first 2048 threads
    if (p < 2048){
        int j2 = p >> 6, cp = p & 63;
        int row = 2*cp + (j2 >= 16 ? 1 : 0);
        int j = j2 & 15;
        g_w2t[j2][cp] = ((const ulonglong2*)(w2 + row*64))[j];
    }
    {
        int b = p >> 12, n = p & 4095;
        const float* xb = x + b*6*N_ + n;
        float x0=xb[0], x1=xb[N_], x2=xb[2*N_], x3=xb[3*N_], x4=xb[4*N_], x5=xb[5*N_];
        g_xp[p]       = make_float2(x0,x1);
        g_xp[PTS+p]   = make_float2(x2,x3);
        g_xp[2*PTS+p] = make_float2(x4,x5);
        g_xx[p] = x0*x0+x1*x1+x2*x2+x3*x3+x4*x4+x5*x5;
    }
    int o = t & 63;
    int pbase = blockIdx.x*256;
    for (int pi = (t>>6); pi < 256; pi += 4){
        int pp = pbase + pi;
        int bb = pp >> 12, nn = pp & 4095;
        const float* xp = x + bb*6*N_ + nn;
        float y0=xp[0], y1=xp[N_], y2=xp[2*N_], y3=xp[3*N_], y4=xp[4*N_], y5=xp[5*N_];
        const float* A = wa + o*6;
        const float* D = wd + o*6;
        g_nb[pp*64+o] = y0*A[0]+y1*A[1]+y2*A[2]+y3*A[3]+y4*A[4]+y5*A[5];
        g_cc[pp*64+o] = y0*D[0]+y1*D[1]+y2*D[2]+y3*D[3]+y4*D[4]+y5*D[5];
    }
}

// ---------------- kernel 1: KNN top-20 (4 queries/warp, short insert chain) -------
__global__ void __launch_bounds__(512) k_knn(){
    int b   = blockIdx.x >> 6;
    int sec = blockIdx.x & 63;
    int w    = threadIdx.x >> 5;
    int lane = threadIdx.x & 31;
    int base = b*N_;
    const float2* xp0 = g_xp + base;
    const float2* xp1 = g_xp + PTS + base;
    const float2* xp2 = g_xp + 2*PTS + base;
    const float*  xxp = g_xx + base;

    int n0 = sec*64 + w*4;
    float q[4][6]; float lv[4]; int li[4]; float minv[4];
    #pragma unroll
    for (int j=0;j<4;j++){
        float2 a = xp0[n0+j], c = xp1[n0+j], e = xp2[n0+j];
        q[j][0]=a.x; q[j][1]=a.y; q[j][2]=c.x; q[j][3]=c.y; q[j][4]=e.x; q[j][5]=e.y;
        lv[j] = -3.4e38f; li[j] = 0; minv[j] = -3.4e38f;
    }

    for (int mb = 0; mb < N_; mb += 32){
        int m = mb + lane;
        float2 a = xp0[m], c = xp1[m], e = xp2[m];
        float xxm = xxp[m];
        float v[4];
        #pragma unroll
        for (int j=0;j<4;j++){
            float d = q[j][0]*a.x + q[j][1]*a.y + q[j][2]*c.x
                    + q[j][3]*c.y + q[j][4]*e.x + q[j][5]*e.y;
            v[j] = 2.f*d - xxm;
        }
        #pragma unroll
        for (int j=0;j<4;j++){
            unsigned cand = __ballot_sync(FULLMASK, v[j] > minv[j]);
            bool any = (cand != 0u);
            while (cand){
                int src = __ffs(cand)-1; cand &= cand-1;
                float cv = __shfl_sync(FULLMASK, v[j], src);
                float pv = __shfl_up_sync(FULLMASK, lv[j], 1);
                int   pq = __shfl_up_sync(FULLMASK, li[j], 1);
                unsigned lt = __ballot_sync(FULLMASK, lv[j] < cv) & 0xFFFFFu;
                if (lt){                              // warp-uniform
                    int pos = __ffs(lt)-1;            // in [0,19]
                    if (lane > pos && lane < KNN){ lv[j]=pv; li[j]=pq; }
                    if (lane == pos)             { lv[j]=cv; li[j]=mb+src; }
                }
            }
            if (any) minv[j] = __shfl_sync(FULLMASK, lv[j], 19);
        }
    }
    #pragma unroll
    for (int j=0;j<4;j++)
        if (lane < KNN) g_idx[(base + n0 + j)*KNN + lane] = li[j];
}

// ---------------- kernel 2: z1 channel stats + bn1 finalize (last block) ----------------
__global__ void __launch_bounds__(256) k_stats1(const float* __restrict__ ga,
                                                const float* __restrict__ be){
    int t = threadIdx.x, o = t & 63, grp = t >> 6;
    float s = 0.f, ss = 0.f;
    for (int pi = blockIdx.x*4 + grp; pi < PTS; pi += 4096){
        float ccv = g_cc[pi*64 + o];
        int bbase = (pi >> 12) << 12;
        const int* ip = g_idx + pi*KNN;
        #pragma unroll
        for (int k=0;k<KNN;k++){
            int r = ip[k];
            float v = g_nb[(bbase + r)*64 + o] + ccv;
            s += v; ss += v*v;
        }
    }
    __shared__ float sh[256], sh2[256];
    sh[t] = s; sh2[t] = ss;
    __syncthreads();
    if (t < 64){
        atomicAdd(&g_s[t],    sh[t]+sh[t+64]+sh[t+128]+sh[t+192]);
        atomicAdd(&g_s[64+t], sh2[t]+sh2[t+64]+sh2[t+128]+sh2[t+192]);
    }
    __threadfence();
    __syncthreads();
    __shared__ int lastb;
    if (t == 0) lastb = (atomicAdd(&g_c0, 1) == (int)gridDim.x - 1);
    __syncthreads();
    if (lastb){
        if (t < 64){
            float cnt = (float)(PTS*KNN);
            float m = g_s[t]/cnt;
            float var = g_s[64+t]/cnt - m*m;
            float a = ga[t]*rsqrtf(var + 1e-5f);
            g_ab[t]    = a;
            g_ab[64+t] = be[t] - m*a;
        }
        if (t == 0) g_c0 = 0;
    }
}

// ---------------- kernel 3: conv2, persistent (grid 444), coalesced weights ----------
// 128 threads: t = (khalf<<6) | cpair. Thread owns channels 2cp,2cp+1 for k-half kh.
#define C2_TILES 2048
__global__ void __launch_bounds__(128) k_conv2(const float* __restrict__ ga,
                                               const float* __restrict__ be){
    int t = threadIdx.x;
    int kh = t >> 6;          // k in [kh*10, kh*10+10)
    int cp = t & 63;          // channel pair -> channels 2cp, 2cp+1
    ull w0[32], w1[32];
    #pragma unroll
    for (int j=0;j<16;j++){
        ulonglong2 v0 = g_w2t[j][cp];    w0[2*j]=v0.x; w0[2*j+1]=v0.y;
        ulonglong2 v1 = g_w2t[16+j][cp]; w1[2*j]=v1.x; w1[2*j+1]=v1.y;
    }
    __shared__ __align__(16) float h1[4][20*64];   // 20KB
    __shared__ float mx[2][4][128];                // partial maxes per k-half
    float a1 = g_ab[cp], b1 = g_ab[64+cp];
    float s0=0.f, ss0=0.f, s1=0.f, ss1=0.f;

    for (int tile = blockIdx.x; tile < C2_TILES; tile += gridDim.x){
        int p0 = tile*16;
        for (int ph = 0; ph < 4; ++ph){
            int pb = p0 + ph*4;
            __syncthreads();
            if (ph > 0 && kh == 0){
                #pragma unroll
                for (int pp=0;pp<4;pp++){
                    int pi = pb - 4 + pp;
                    float2 v;
                    v.x = fmaxf(mx[0][pp][2*cp],   mx[1][pp][2*cp]);
                    v.y = fmaxf(mx[0][pp][2*cp+1], mx[1][pp][2*cp+1]);
                    *(float2*)(g_m2 + pi*128 + 2*cp) = v;
                }
            }
            #pragma unroll
            for (int pp=0;pp<4;pp++){
                int pi = pb + pp;
                int bbase = (pi >> 12) << 12;
                float ccv = g_cc[pi*64 + cp];
                const int* ip = g_idx + pi*KNN;
                #pragma unroll
                for (int kk=0;kk<10;kk++){
                    int k = kh*10 + kk;
                    int r = ip[k];
                    h1[pp][k*64 + cp] = lrelu(fmaf(a1, g_nb[(bbase + r)*64 + cp] + ccv, b1));
                }
            }
            __syncthreads();
            #pragma unroll
            for (int pp=0;pp<4;pp++){
                float m0 = -3.4e38f, m1 = -3.4e38f;
                for (int kk=0;kk<10;kk++){
                    int k = kh*10 + kk;
                    const ulonglong2* hp = (const ulonglong2*)(h1[pp] + k*64);
                    ull A0=0ull, B0=0ull, A1=0ull, B1=0ull;
                    #pragma unroll
                    for (int j=0;j<16;j++){
                        ulonglong2 h = hp[j];
                        ffma2(A0, w0[2*j],   h.x);
                        ffma2(B0, w0[2*j+1], h.y);
                        ffma2(A1, w1[2*j],   h.x);
                        ffma2(B1, w1[2*j+1], h.y);
                    }
                    fadd2(A0, B0); fadd2(A1, B1);
                    float z0 = f2lo(A0) + f2hi(A0);
                    float z1 = f2lo(A1) + f2hi(A1);
                    s0 += z0; ss0 += z0*z0; m0 = fmaxf(m0, z0);
                    s1 += z1; ss1 += z1*z1; m1 = fmaxf(m1, z1);
                }
                mx[kh][pp][2*cp]   = m0;
                mx[kh][pp][2*cp+1] = m1;
            }
        }
        __syncthreads();
        if (kh == 0){
            #pragma unroll
            for (int pp=0;pp<4;pp++){
                int pi = p0 + 12 + pp;
                float2 v;
                v.x = fmaxf(mx[0][pp][2*cp],   mx[1][pp][2*cp]);
                v.y = fmaxf(mx[0][pp][2*cp+1], mx[1][pp][2*cp+1]);
                *(float2*)(g_m2 + pi*128 + 2*cp) = v;
            }
        }
    }
    atomicAdd(&g_s[128+2*cp],   s0);
    atomicAdd(&g_s[128+2*cp+1], s1);
    atomicAdd(&g_s[256+2*cp],   ss0);
    atomicAdd(&g_s[256+2*cp+1], ss1);
    __threadfence();
    __syncthreads();
    __shared__ int lastb;
    if (t == 0) lastb = (atomicAdd(&g_c1, 1) == (int)gridDim.x - 1);
    __syncthreads();
    if (lastb){
        float cnt = (float)(PTS*KNN);
        float m = g_s[128+t]/cnt;
        float var = g_s[256+t]/cnt - m*m;
        float a = ga[t]*rsqrtf(var + 1e-5f);
        g_ab[128+t] = a;
        g_ab[256+t] = be[t] - m*a;
        if (t == 0) g_c1 = 0;
    }
}

// ---------------- kernel 4: conv3, persistent (grid 444), coalesced weights --------
// 2048 units: u = chunk(8) | bb(8) | sec(32); unit = 128 points, 128 channels.
// 128 threads: kh=t&1 input half, p2=t>>1 -> channels chunk*128+2p2,+1.
#define C3_UNITS 2048
__global__ void __launch_bounds__(128) k_conv3(const float* __restrict__ ga,
                                               const float* __restrict__ be){
    int t = threadIdx.x;
    int kh = t & 1;
    __shared__ __align__(16) float h2[8*128];
    __shared__ float sab[128], sbb[128];
    sab[t] = g_ab[128+t]; sbb[t] = g_ab[256+t];
    __syncthreads();

    for (int u = blockIdx.x; u < C3_UNITS; u += gridDim.x){
        int chunk = u & 7;
        int bb    = (u >> 3) & 7;
        int sec   = u >> 6;            // 0..31
        ull w0[32], w1[32];
        #pragma unroll
        for (int j=0;j<16;j++){
            ulonglong2 v0 = g_w3t[chunk][j][t];    w0[2*j]=v0.x; w0[2*j+1]=v0.y;
            ulonglong2 v1 = g_w3t[chunk][16+j][t]; w1[2*j]=v1.x; w1[2*j+1]=v1.y;
        }
        float s=0.f, ss=0.f, maxv=-3.4e38f;
        int pbase = (bb << 12) + sec*128;
        for (int pp = 0; pp < 128; pp += 8){
            __syncthreads();
            #pragma unroll
            for (int i = t; i < 8*128; i += 128){
                int pl = i >> 7, ch = i & 127;
                h2[i] = lrelu(fmaf(sab[ch], g_m2[(pbase+pp+pl)*128 + ch], sbb[ch]));
            }
            __syncthreads();
            #pragma unroll 2
            for (int pl=0; pl<8; ++pl){
                const ulonglong2* hp = (const ulonglong2*)(h2 + pl*128 + kh*64);
                ull A0=0ull, B0=0ull, A1=0ull, B1=0ull;
                #pragma unroll
                for (int j=0;j<16;j++){
                    ulonglong2 h = hp[j];
                    ffma2(A0, w0[2*j],   h.x);
                    ffma2(B0, w0[2*j+1], h.y);
                    ffma2(A1, w1[2*j],   h.x);
                    ffma2(B1, w1[2*j+1], h.y);
                }
                fadd2(A0, B0); fadd2(A1, B1);
                float z0p = f2lo(A0) + f2hi(A0);
                float z1p = f2lo(A1) + f2hi(A1);
                float z0 = z0p + __shfl_xor_sync(FULLMASK, z0p, 1);
                float z1 = z1p + __shfl_xor_sync(FULLMASK, z1p, 1);
                float z = kh ? z1 : z0;
                s += z; ss += z*z;
                maxv = fmaxf(maxv, z);
            }
        }
        int ch = chunk*128 + t;
        atomicAdd(&g_s[384+ch],  s);
        atomicAdd(&g_s[1408+ch], ss);
        atomicMax(&g_z3e[bb*1024 + ch], fenc(maxv));
    }
    __threadfence();
    __syncthreads();
    __shared__ int lastb;
    if (t == 0) lastb = (atomicAdd(&g_c2, 1) == (int)gridDim.x - 1);
    __syncthreads();
    if (lastb){
        float cnt = (float)PTS;
        for (int c = t; c < 1024; c += 128){
            float m = g_s[384+c]/cnt;
            float var = g_s[1408+c]/cnt - m*m;
            float a = ga[c]*rsqrtf(var + 1e-5f);
            float bo = be[c] - m*a;
            #pragma unroll
            for (int b=0;b<B_;b++)
                g_g[b*1024+c] = lrelu(fmaf(a, fdec(g_z3e[b*1024+c]), bo));
        }
        if (t == 0) g_c2 = 0;
    }
}

// ---------------- kernel 5: fc1 + bn4 + lrelu ----------------
__global__ void __launch_bounds__(128) k_fc1(const float* __restrict__ fw,
                                             const float* __restrict__ g4g,
                                             const float* __restrict__ g4b){
    __shared__ float gs[B_*1024];
    int t = threadIdx.x;
    for (int i=t;i<B_*1024;i+=128) gs[i] = g_g[i];
    __syncthreads();
    int w = t >> 5, lane = t & 31;
    for (int jj=0;jj<2;jj++){
        int j = blockIdx.x*8 + w*2 + jj;
        const float* wrow = fw + j*1024;
        float acc[8] = {0,0,0,0,0,0,0,0};
        for (int c=lane;c<1024;c+=32){
            float wv = wrow[c];
            #pragma unroll
            for (int b=0;b<8;b++) acc[b] += gs[b*1024+c]*wv;
        }
        #pragma unroll
        for (int b=0;b<8;b++){
            #pragma unroll
            for (int off=16;off;off>>=1) acc[b] += __shfl_xor_sync(FULLMASK, acc[b], off);
        }
        if (lane == 0){
            float m=0.f;
            #pragma unroll
            for (int b=0;b<8;b++) m += acc[b];
            m *= 0.125f;
            float var=0.f;
            #pragma unroll
            for (int b=0;b<8;b++){ float d = acc[b]-m; var += d*d; }
            var *= 0.125f;
            float a = g4g[j]*rsqrtf(var + 1e-5f);
            float bo = g4b[j] - m*a;
            #pragma unroll
            for (int b=0;b<8;b++) g_g4[b*512+j] = lrelu(a*acc[b] + bo);
        }
    }
}

// ---------------- kernel 6: fc2+bn5+lrelu, fc3/fc4 -> mat/bias ----------------
__global__ void __launch_bounds__(256) k_head(const float* __restrict__ f2w,
        const float* __restrict__ g5g, const float* __restrict__ g5b,
        const float* __restrict__ f3w, const float* __restrict__ f3b,
        const float* __restrict__ f4w, const float* __restrict__ f4b){
    __shared__ float g4s[B_*512];
    __shared__ float g5s[B_*256];
    int t = threadIdx.x, w = t >> 5, lane = t & 31;
    for (int i=t;i<B_*512;i+=256) g4s[i] = g_g4[i];
    __syncthreads();
    for (int jj=0;jj<32;jj++){
        int j = w*32 + jj;
        const float* wrow = f2w + j*512;
        float acc[8] = {0,0,0,0,0,0,0,0};
        for (int c=lane;c<512;c+=32){
            float wv = wrow[c];
            #pragma unroll
            for (int b=0;b<8;b++) acc[b] += g4s[b*512+c]*wv;
        }
        #pragma unroll
        for (int b=0;b<8;b++){
            #pragma unroll
            for (int off=16;off;off>>=1) acc[b] += __shfl_xor_sync(FULLMASK, acc[b], off);
        }
        if (lane == 0){
            float m=0.f;
            #pragma unroll
            for (int b=0;b<8;b++) m += acc[b];
            m *= 0.125f;
            float var=0.f;
            #pragma unroll
            for (int b=0;b<8;b++){ float d = acc[b]-m; var += d*d; }
            var *= 0.125f;
            float a = g5g[j]*rsqrtf(var + 1e-5f);
            float bo = g5b[j] - m*a;
            #pragma unroll
            for (int b=0;b<8;b++) g5s[b*256+j] = lrelu(a*acc[b] + bo);
        }
    }
    __syncthreads();
    for (int i=0;i<12;i++){
        int task = w*12 + i;           // 0..95
        int b = task / 12, jo = task % 12;
        const float* wrow = (jo < 9) ? (f3w + jo*256) : (f4w + (jo-9)*256);
        float acc = 0.f;
        for (int c=lane;c<256;c+=32) acc += g5s[b*256+c]*wrow[c];
        #pragma unroll
        for (int off=16;off;off>>=1) acc += __shfl_xor_sync(FULLMASK, acc, off);
        if (lane == 0){
            if (jo < 9){
                int r = jo/3, cc = jo%3;
                g_mat[b*9+jo] = acc + f3b[jo] + (r==cc ? 1.f : 0.f);
            } else {
                g_bias[b*3 + (jo-9)] = acc + f4b[jo-9];
            }
        }
    }
}

// ---------------- kernel 7: apply 3x3 transform ----------------
__global__ void k_out(const float* __restrict__ x, float* __restrict__ out){
    int p = blockIdx.x*1024 + threadIdx.x;   // 32 blocks x 1024 = 32768
    int b = p >> 12, n = p & 4095;
    const float* xb = x + b*6*N_ + n;
    float x0 = xb[0], x1 = xb[N_], x2 = xb[2*N_];
    const float* M  = g_mat + b*9;
    const float* Bi = g_bias + b*3;
    float* ob = out + b*3*N_ + n;
    ob[0]    = x0*M[0] + x1*M[3] + x2*M[6] + Bi[0];
    ob[N_]   = x0*M[1] + x1*M[4] + x2*M[7] + Bi[1];
    ob[2*N_] = x0*M[2] + x1*M[5] + x2*M[8] + Bi[2];
}

// ---------------- launch ----------------
extern "C" void kernel_launch(void* const* d_in, const int* in_sizes, int n_in,
                              void* d_out, int out_size){
    const float* x     = (const float*)d_in[0];
    const float* w1    = (const float*)d_in[1];
    const float* bn1g  = (const float*)d_in[2];
    const float* bn1b  = (const float*)d_in[3];
    const float* w2    = (const float*)d_in[4];
    const float* bn2g  = (const float*)d_in[5];
    const float* bn2b  = (const float*)d_in[6];
    const float* w3    = (const float*)d_in[7];
    const float* bn3g  = (const float*)d_in[8];
    const float* bn3b  = (const float*)d_in[9];
    const float* fc1w  = (const float*)d_in[10];
    const float* bn4g  = (const float*)d_in[11];
    const float* bn4b  = (const float*)d_in[12];
    const float* fc2w  = (const float*)d_in[13];
    const float* bn5g  = (const float*)d_in[14];
    const float* bn5b  = (const float*)d_in[15];
    const float* fc3w  = (const float*)d_in[16];
    const float* fc3b  = (const float*)d_in[17];
    const float* fc4w  = (const float*)d_in[18];
    const float* fc4b  = (const float*)d_in[19];
    float* out = (float*)d_out;

    k_prep  <<<128, 256>>>(x, w1, w2, w3);  // 1
    k_knn   <<<B_*64, 512>>>();             // 2
    k_stats1<<<1024, 256>>>(bn1g, bn1b);    // 3
    k_conv2 <<<444, 128>>>(bn2g, bn2b);     // 4  <- ncu capture slot
    k_conv3 <<<444, 128>>>(bn3g, bn3b);     // 5
    k_fc1   <<<64, 128>>>(fc1w, bn4g, bn4b);
    k_head  <<<1, 256>>>(fc2w, bn5g, bn5b, fc3w, fc3b, fc4w, fc4b);
    k_out   <<<32, 1024>>>(x, out);
}